// round 11
// baseline (speedup 1.0000x reference)
#include <cuda_runtime.h>
#include <cstdint>

// Problem constants
#define BB 64      // batch
#define TT 512     // seq len
#define DD 256     // input dim
#define UU 512     // units
#define MM 64      // memory slots
#define NN 2112    // 4*U + M
#define KK 768     // D + U

#define NBLK 132   // 66 n-stripes x 2 batch-halves

// dynamic smem layout (float offsets)
//  s_W   : [768][32]              24576 f  (persistent weight stripe)
//  s_a   : 2 x [128][34]           8704 f  (A double buffer; aliased by s_p: 256x17 u64)
//  s_mem : [64][256]              16384 f  (block-private shift-register memory)
#define SA_STRIDE 34
#define SA_BUF 4352
#define SA_OFF 24576
#define SM_OFF 33280
#define SMEM_FLOATS 49664
#define SMEM_BYTES (SMEM_FLOATS * 4)   // 198656 B

// -------- device scratch (no allocations allowed) --------
__device__ float g_W[KK * NN];
__device__ float g_b[NN];
__device__ float g_h[BB * UU];
__device__ float g_z[BB * NN];
__device__ unsigned g_arrive[NBLK * 8];   // one flag per block, 32B apart
__device__ unsigned g_epoch = 0;

// =====================================================================
// Init: pack W/U/b into [768 x 2112], zero h.
// =====================================================================
__global__ void init_kernel(
    const float* __restrict__ Wi, const float* __restrict__ Ui, const float* __restrict__ bi,
    const float* __restrict__ Wf, const float* __restrict__ Uf, const float* __restrict__ bf,
    const float* __restrict__ Wo, const float* __restrict__ Uo, const float* __restrict__ bo,
    const float* __restrict__ Wc, const float* __restrict__ Uc, const float* __restrict__ bc,
    const float* __restrict__ We, const float* __restrict__ Ue, const float* __restrict__ be)
{
    int stride = gridDim.x * blockDim.x;
    int t0 = blockIdx.x * blockDim.x + threadIdx.x;

    for (int i = t0; i < KK * NN; i += stride) {
        int k = i / NN;
        int n = i - k * NN;
        float v;
        if (n < 4 * UU) {
            int g = n >> 9;
            int col = n & (UU - 1);
            const float* s;
            if (k < DD) {
                s = (g == 0) ? Wi : (g == 1) ? Wf : (g == 2) ? Wo : Wc;
                v = s[k * UU + col];
            } else {
                s = (g == 0) ? Ui : (g == 1) ? Uf : (g == 2) ? Uo : Uc;
                v = s[(k - DD) * UU + col];
            }
        } else {
            int col = n - 4 * UU;
            v = (k < DD) ? We[k * MM + col] : Ue[(k - DD) * MM + col];
        }
        g_W[i] = v;
    }
    for (int i = t0; i < NN; i += stride) {
        float v;
        if (i < 4 * UU) {
            int g = i >> 9;
            int col = i & (UU - 1);
            v = (g == 0) ? bi[col] : (g == 1) ? bf[col] : (g == 2) ? bo[col] : bc[col];
        } else {
            v = be[i - 4 * UU];
        }
        g_b[i] = v;
    }
    for (int i = t0; i < BB * UU; i += stride) g_h[i] = 0.0f;
}

// =====================================================================
// Grid-wide barrier WITHOUT contended atomics:
//   every block release-stores its own padded flag (no serialization);
//   block 0 warp 0 sweeps all flags (MLP'd acquire loads), then
//   release-stores the epoch; everyone else acquire-polls the epoch.
// Flags are monotone counters -> no reset, no reuse race.
// =====================================================================
__device__ __forceinline__ void grid_barrier(unsigned* my_epoch)
{
    __syncthreads();
    const unsigned target = *my_epoch + 1u;

    if (threadIdx.x == 0) {
        asm volatile("st.release.gpu.global.u32 [%0], %1;"
                     :: "l"(&g_arrive[blockIdx.x * 8]), "r"(target) : "memory");
    }

    if (blockIdx.x == 0) {
        if (threadIdx.x < 32) {
            for (;;) {
                int ok = 1;
                for (int f = threadIdx.x; f < NBLK; f += 32) {
                    unsigned v;
                    asm volatile("ld.acquire.gpu.global.u32 %0, [%1];"
                                 : "=r"(v) : "l"(&g_arrive[f * 8]) : "memory");
                    ok &= ((int)(v - target) >= 0);
                }
                if (__all_sync(0xffffffffu, ok)) break;
            }
            if (threadIdx.x == 0) {
                asm volatile("st.release.gpu.global.u32 [%0], %1;"
                             :: "l"(&g_epoch), "r"(target) : "memory");
            }
        }
    } else {
        if (threadIdx.x == 0) {
            unsigned e;
            do {
                asm volatile("ld.acquire.gpu.global.u32 %0, [%1];"
                             : "=r"(e) : "l"(&g_epoch) : "memory");
            } while ((int)(e - target) < 0);
        }
    }

    *my_epoch = target;
    __syncthreads();
}

__device__ __forceinline__ void ffma2(unsigned long long& acc,
                                      unsigned long long a2,
                                      unsigned long long b2)
{
    asm("fma.rn.f32x2 %0, %1, %2, %0;" : "+l"(acc) : "l"(a2), "l"(b2));
}

__device__ __forceinline__ float rcpa(float x)
{
    float r; asm("rcp.approx.f32 %0, %1;" : "=f"(r) : "f"(x)); return r;
}
__device__ __forceinline__ float fsig(float x)
{
    return rcpa(1.0f + __expf(-x));
}
__device__ __forceinline__ float ftanh(float x)
{
    return 2.0f * rcpa(1.0f + __expf(-2.0f * x)) - 1.0f;
}

// 16 k-steps: lane tile 4m x 8n (16 packed f32x2 accumulators).
// acc[mi*4+p] = m row (4*mq+mi), packed n cols (8*nq+2p, 8*nq+2p+1).
__device__ __forceinline__ void compute_chunk(const float* __restrict__ sa,
                                              const float* __restrict__ sw,
                                              unsigned long long acc[16])
{
#pragma unroll
    for (int r = 0; r < 16; ++r) {
        float2 a01 = *(const float2*)(sa + r * SA_STRIDE);
        float2 a23 = *(const float2*)(sa + r * SA_STRIDE + 2);
        const ulonglong2* bw = (const ulonglong2*)(sw + r * 32);
        ulonglong2 bv0 = bw[0];
        ulonglong2 bv1 = bw[1];
        unsigned long long a2_0, a2_1, a2_2, a2_3;
        asm("mov.b64 %0, {%1, %1};" : "=l"(a2_0) : "f"(a01.x));
        asm("mov.b64 %0, {%1, %1};" : "=l"(a2_1) : "f"(a01.y));
        asm("mov.b64 %0, {%1, %1};" : "=l"(a2_2) : "f"(a23.x));
        asm("mov.b64 %0, {%1, %1};" : "=l"(a2_3) : "f"(a23.y));
        ffma2(acc[0],  a2_0, bv0.x); ffma2(acc[1],  a2_0, bv0.y);
        ffma2(acc[2],  a2_0, bv1.x); ffma2(acc[3],  a2_0, bv1.y);
        ffma2(acc[4],  a2_1, bv0.x); ffma2(acc[5],  a2_1, bv0.y);
        ffma2(acc[6],  a2_1, bv1.x); ffma2(acc[7],  a2_1, bv1.y);
        ffma2(acc[8],  a2_2, bv0.x); ffma2(acc[9],  a2_2, bv0.y);
        ffma2(acc[10], a2_2, bv1.x); ffma2(acc[11], a2_2, bv1.y);
        ffma2(acc[12], a2_3, bv0.x); ffma2(acc[13], a2_3, bv0.y);
        ffma2(acc[14], a2_3, bv1.x); ffma2(acc[15], a2_3, bv1.y);
    }
}

// =====================================================================
// Persistent kernel: 512 x { GEMM -> barrier -> pointwise -> barrier }.
// Block = (n-stripe, batch-half): z[32m x 32n] over K=768.
// 8 warps split K (96 each, staged 16 at a time, double-buffered,
// ONE syncthreads per chunk).
// =====================================================================
__global__ __launch_bounds__(256, 1) void xlstm_persistent(
    const float* __restrict__ x, float* __restrict__ out)
{
    extern __shared__ float smem[];
    float* s_W  = smem;
    float* s_aF = smem + SA_OFF;
    unsigned long long* s_p  = (unsigned long long*)(smem + SA_OFF); // alias
    float* s_mem = smem + SM_OFF;
    __shared__ float s_e[MM];
    __shared__ float s_ew[MM];

    const int tid   = threadIdx.x;
    const int lane  = tid & 31;
    const int warp  = tid >> 5;           // k-group 0..7
    const int blk   = blockIdx.x;
    const int n0    = (blk >> 1) * 32;
    const int m0    = (blk & 1) * 32;
    const int mq    = lane >> 2;          // 0..7
    const int nq    = lane & 3;           // 0..3
    const int qk    = nq * 4;             // k offset of this lane's float4
    const int kwarp = warp * 96;

    // ---- load W stripe into smem once (persistent across all 512 steps)
#pragma unroll 4
    for (int q = 0; q < 96; ++q) {
        int i = tid + q * 256;            // 0..24575
        int k = i >> 5, n = i & 31;
        s_W[i] = g_W[k * NN + n0 + n];
    }
    // ---- zero block-private memory
    for (int i = tid; i < MM * 256; i += 256) s_mem[i] = 0.0f;

    // ---- hoist bias for this thread's two epilogue outputs
    float2 bias0 = *(const float2*)(g_b + n0 + 2 * (tid & 15));
    float2 bias1 = bias0;                 // np identical for both q (o & 15)

    unsigned my_epoch;
    {
        unsigned e0;
        asm volatile("ld.acquire.gpu.global.u32 %0, [%1];"
                     : "=r"(e0) : "l"(&g_epoch) : "memory");
        my_epoch = e0;                    // all threads read the same settled value
    }
    __syncthreads();

#define LOAD_CHUNK(cc)                                                        \
    {                                                                         \
        int kb = kwarp + (cc) * 16 + qk;                                      \
        if (kb < DD) {                                                        \
            const float* bp = x + (size_t)(m0 + mq) * (TT * DD)               \
                                + (size_t)t * DD + kb;                        \
            v0 = *(const float4*)(bp);                                        \
            v1 = *(const float4*)(bp + (size_t)8  * (TT * DD));               \
            v2 = *(const float4*)(bp + (size_t)16 * (TT * DD));               \
            v3 = *(const float4*)(bp + (size_t)24 * (TT * DD));               \
        } else {                                                              \
            const float* hp = g_h + (m0 + mq) * UU + (kb - DD);               \
            v0 = __ldcg((const float4*)(hp));                                 \
            v1 = __ldcg((const float4*)(hp + 8  * UU));                       \
            v2 = __ldcg((const float4*)(hp + 16 * UU));                       \
            v3 = __ldcg((const float4*)(hp + 24 * UU));                       \
        }                                                                     \
    }

#define STORE_CHUNK(bsel)                                                     \
    {                                                                         \
        float* d = s_aF + (bsel) * SA_BUF                                     \
                 + (warp * 16 + qk) * SA_STRIDE + mq;                         \
        d[0 * SA_STRIDE + 0]  = v0.x; d[1 * SA_STRIDE + 0]  = v0.y;           \
        d[2 * SA_STRIDE + 0]  = v0.z; d[3 * SA_STRIDE + 0]  = v0.w;           \
        d[0 * SA_STRIDE + 8]  = v1.x; d[1 * SA_STRIDE + 8]  = v1.y;           \
        d[2 * SA_STRIDE + 8]  = v1.z; d[3 * SA_STRIDE + 8]  = v1.w;           \
        d[0 * SA_STRIDE + 16] = v2.x; d[1 * SA_STRIDE + 16] = v2.y;           \
        d[2 * SA_STRIDE + 16] = v2.z; d[3 * SA_STRIDE + 16] = v2.w;           \
        d[0 * SA_STRIDE + 24] = v3.x; d[1 * SA_STRIDE + 24] = v3.y;           \
        d[2 * SA_STRIDE + 24] = v3.z; d[3 * SA_STRIDE + 24] = v3.w;           \
    }

    for (int t = 0; t < TT; ++t) {
        // ============================ GEMM ============================
        unsigned long long acc[16];
#pragma unroll
        for (int q = 0; q < 16; ++q) acc[q] = 0ull;

        float4 v0, v1, v2, v3;
        LOAD_CHUNK(0)

        // single-sync double-buffered pipeline:
        //   store(c) -> sync -> load(c+1) -> compute(c)
#pragma unroll 1
        for (int c = 0; c < 6; ++c) {
            STORE_CHUNK(c & 1)
            __syncthreads();
            if (c < 5) LOAD_CHUNK(c + 1)
            compute_chunk(s_aF + (c & 1) * SA_BUF + (warp * 16) * SA_STRIDE + 4 * mq,
                          s_W + (kwarp + c * 16) * 32 + 8 * nq, acc);
        }

        // ---- cross-kg reduction: per-thread padded u64 row (conflict-free)
        __syncthreads();
        {
            unsigned long long* pp = s_p + (size_t)tid * 17;
#pragma unroll
            for (int q = 0; q < 16; ++q) pp[q] = acc[q];
        }
        __syncthreads();
        // readers: output u64 (m, np): src lane = 4*(m>>2)+(np>>2),
        //          acc idx = (m&3)*4 + (np&3)
#pragma unroll
        for (int q2 = 0; q2 < 2; ++q2) {
            int o   = tid + q2 * 256;     // 0..511
            int m   = o >> 4;             // 0..31
            int np  = o & 15;             // u64 col pair
            int src = (4 * (m >> 2) + (np >> 2)) * 17 + (m & 3) * 4 + (np & 3);
            float sx0 = 0.f, sy0 = 0.f, sx1 = 0.f, sy1 = 0.f;
#pragma unroll
            for (int kg = 0; kg < 8; kg += 2) {
                unsigned long long u0 = s_p[(size_t)(kg * 32) * 17 + src];
                unsigned long long u1 = s_p[(size_t)((kg + 1) * 32) * 17 + src];
                float l0, h0, l1, h1;
                asm("mov.b64 {%0, %1}, %2;" : "=f"(l0), "=f"(h0) : "l"(u0));
                asm("mov.b64 {%0, %1}, %2;" : "=f"(l1), "=f"(h1) : "l"(u1));
                sx0 += l0; sy0 += h0;
                sx1 += l1; sy1 += h1;
            }
            float2 r;
            float2 bb = q2 ? bias1 : bias0;
            r.x = (sx0 + sx1) + bb.x;
            r.y = (sy0 + sy1) + bb.y;
            *(float2*)(g_z + (size_t)(m0 + m) * NN + n0 + 2 * np) = r;
        }

        grid_barrier(&my_epoch);

        // ========================== pointwise =========================
        if (blk < 2 * BB) {
            const int b    = blk >> 1;
            const int half = blk & 1;

            if (tid < 32) {
                float z0 = __ldcg(&g_z[b * NN + 4 * UU + tid]);
                float z1 = __ldcg(&g_z[b * NN + 4 * UU + 32 + tid]);
                float mx = fmaxf(z0, z1);
#pragma unroll
                for (int o = 16; o > 0; o >>= 1)
                    mx = fmaxf(mx, __shfl_xor_sync(0xffffffffu, mx, o));
                float e0 = __expf(z0 - mx);
                float e1 = __expf(z1 - mx);
                float sm2 = e0 + e1;
#pragma unroll
                for (int o = 16; o > 0; o >>= 1)
                    sm2 += __shfl_xor_sync(0xffffffffu, sm2, o);
                float inv = rcpa(sm2);
                s_e[tid]      = e0 * inv;
                s_e[tid + 32] = e1 * inv;
            }
            __syncthreads();
            // physical slot s holds c from step t'=s mod 64; age m = t-1-t'
            if (tid < MM) s_ew[tid] = s_e[(t - 1 - tid) & (MM - 1)];
            __syncthreads();

            const int u  = half * 256 + tid;
            const int zb = b * NN;
            float zi = __ldcg(&g_z[zb + u]);
            float zf = __ldcg(&g_z[zb + UU + u]);
            float zo = __ldcg(&g_z[zb + 2 * UU + u]);
            float zc = __ldcg(&g_z[zb + 3 * UU + u]);

            float gi = fsig(zi);
            float gf = fsig(zf);
            float go = fsig(zo);
            float ct = ftanh(zc);

            const float* mb = s_mem + tid;
            float c0 = 0.f, c1 = 0.f, c2 = 0.f, c3 = 0.f;
#pragma unroll
            for (int s = 0; s < MM; s += 4) {
                c0 += s_ew[s + 0] * mb[(s + 0) * 256];
                c1 += s_ew[s + 1] * mb[(s + 1) * 256];
                c2 += s_ew[s + 2] * mb[(s + 2) * 256];
                c3 += s_ew[s + 3] * mb[(s + 3) * 256];
            }
            float contrib = (c0 + c1) + (c2 + c3);

            float cc = gf * contrib + gi * ct;
            float hh = go * ftanh(cc);

            s_mem[(t & (MM - 1)) * 256 + tid] = cc;   // overwrite oldest slot
            g_h[b * UU + u] = hh;
            out[(size_t)b * (TT * UU) + (size_t)t * UU + u] = hh;
        }

        grid_barrier(&my_epoch);
    }
#undef LOAD_CHUNK
#undef STORE_CHUNK
}

// =====================================================================
// Launch: 2 graph nodes. No allocations, graph-capturable.
// =====================================================================
extern "C" void kernel_launch(void* const* d_in, const int* in_sizes, int n_in,
                              void* d_out, int out_size)
{
    (void)in_sizes; (void)n_in; (void)out_size;
    const float* x  = (const float*)d_in[0];
    const float* Wi = (const float*)d_in[1];
    const float* Ui = (const float*)d_in[2];
    const float* bi = (const float*)d_in[3];
    const float* Wf = (const float*)d_in[4];
    const float* Uf = (const float*)d_in[5];
    const float* bf = (const float*)d_in[6];
    const float* Wo = (const float*)d_in[7];
    const float* Uo = (const float*)d_in[8];
    const float* bo = (const float*)d_in[9];
    const float* Wc = (const float*)d_in[10];
    const float* Uc = (const float*)d_in[11];
    const float* bc = (const float*)d_in[12];
    const float* We = (const float*)d_in[13];
    const float* Ue = (const float*)d_in[14];
    const float* be = (const float*)d_in[15];
    float* out = (float*)d_out;

    cudaFuncSetAttribute(xlstm_persistent,
                         cudaFuncAttributeMaxDynamicSharedMemorySize, SMEM_BYTES);

    init_kernel<<<1024, 256>>>(Wi, Ui, bi, Wf, Uf, bf, Wo, Uo, bo,
                               Wc, Uc, bc, We, Ue, be);
    xlstm_persistent<<<NBLK, 256, SMEM_BYTES>>>(x, out);
}

// round 12
// speedup vs baseline: 1.2327x; 1.2327x over previous
#include <cuda_runtime.h>
#include <cstdint>

// Problem constants
#define BB 64      // batch
#define TT 512     // seq len
#define DD 256     // input dim
#define UU 512     // units
#define MM 64      // memory slots
#define NN 2112    // 4*U + M  (packed, gate-interleaved)
#define KK 768     // D + U

#define NBLK 132   // 66 stripes x 2 batch-halves; stripes 0..63 gate, 64..65 ze

// dynamic smem layout (float offsets)
//  s_W   : [768][32]    24576 f  (persistent weight stripe)
//  s_a   : 2 x [128][34] 8704 f  (A dbl buffer; aliased by s_p 256x17 u64 and e_s 32x66)
//  s_z   : [32][34]      1088 f  (local z tile, gate blocks)
//  s_mem : [64][256]    16384 f  (block-private shift-register memory)
#define SA_STRIDE 34
#define SA_BUF 4352
#define SA_OFF 24576
#define SZ_OFF 33280
#define SM_OFF 34368
#define SMEM_FLOATS 50752
#define SMEM_BYTES (SMEM_FLOATS * 4)   // 203008 B

// -------- device scratch (no allocations allowed) --------
__device__ float g_W[KK * NN];
__device__ float g_b[NN];
__device__ float g_h[BB * UU];
__device__ float g_zes[2 * 2 * 32 * 32];   // [bh][si][m][32] ze slices
__device__ float g_e[2 * 32 * 64];         // [bh][m][64] softmax weights
__device__ unsigned g_zflag[4 * 8];        // padded flags, monotone
__device__ unsigned g_eflag[4 * 8];
__device__ unsigned g_count = 0;
__device__ unsigned g_epoch = 0;

// =====================================================================
// Init: pack W/U/b into gate-interleaved [768 x 2112], zero h.
// Packed col n: stripe=n>>5, w=n&31.
//   stripe<64 : gate g=w>>3, unit u=stripe*8+(w&7)
//   stripe>=64: ze col = (stripe-64)*32 + w
// =====================================================================
__global__ void init_kernel(
    const float* __restrict__ Wi, const float* __restrict__ Ui, const float* __restrict__ bi,
    const float* __restrict__ Wf, const float* __restrict__ Uf, const float* __restrict__ bf,
    const float* __restrict__ Wo, const float* __restrict__ Uo, const float* __restrict__ bo,
    const float* __restrict__ Wc, const float* __restrict__ Uc, const float* __restrict__ bc,
    const float* __restrict__ We, const float* __restrict__ Ue, const float* __restrict__ be)
{
    int stride = gridDim.x * blockDim.x;
    int t0 = blockIdx.x * blockDim.x + threadIdx.x;

    for (int i = t0; i < KK * NN; i += stride) {
        int k = i / NN;
        int n = i - k * NN;
        int stripe = n >> 5, w = n & 31;
        float v;
        if (stripe < 64) {
            int g = w >> 3;
            int u = stripe * 8 + (w & 7);
            if (k < DD) {
                const float* s = (g == 0) ? Wi : (g == 1) ? Wf : (g == 2) ? Wo : Wc;
                v = s[k * UU + u];
            } else {
                const float* s = (g == 0) ? Ui : (g == 1) ? Uf : (g == 2) ? Uo : Uc;
                v = s[(k - DD) * UU + u];
            }
        } else {
            int col = (stripe - 64) * 32 + w;
            v = (k < DD) ? We[k * MM + col] : Ue[(k - DD) * MM + col];
        }
        g_W[i] = v;
    }
    for (int i = t0; i < NN; i += stride) {
        int stripe = i >> 5, w = i & 31;
        float v;
        if (stripe < 64) {
            int g = w >> 3;
            int u = stripe * 8 + (w & 7);
            v = (g == 0) ? bi[u] : (g == 1) ? bf[u] : (g == 2) ? bo[u] : bc[u];
        } else {
            v = be[(stripe - 64) * 32 + w];
        }
        g_b[i] = v;
    }
    for (int i = t0; i < BB * UU; i += stride) g_h[i] = 0.0f;
}

// =====================================================================
// Grid-wide barrier (R8 atomic version — best measured).
// =====================================================================
__device__ __forceinline__ void grid_barrier(unsigned* my_epoch)
{
    __syncthreads();
    if (threadIdx.x == 0) {
        unsigned target = *my_epoch + 1u;
        unsigned v;
        asm volatile("atom.acq_rel.gpu.global.add.u32 %0, [%1], 1;"
                     : "=r"(v) : "l"(&g_count) : "memory");
        if (v == NBLK - 1) {
            unsigned zero = 0;
            asm volatile("st.relaxed.gpu.global.u32 [%0], %1;"
                         :: "l"(&g_count), "r"(zero) : "memory");
            asm volatile("st.release.gpu.global.u32 [%0], %1;"
                         :: "l"(&g_epoch), "r"(target) : "memory");
        } else {
            unsigned e;
            do {
                asm volatile("ld.acquire.gpu.global.u32 %0, [%1];"
                             : "=r"(e) : "l"(&g_epoch) : "memory");
            } while ((int)(e - target) < 0);
        }
        *my_epoch = target;
    }
    __syncthreads();
}

__device__ __forceinline__ unsigned ld_acq(const unsigned* p)
{
    unsigned v;
    asm volatile("ld.acquire.gpu.global.u32 %0, [%1];" : "=r"(v) : "l"(p) : "memory");
    return v;
}
__device__ __forceinline__ void st_rel(unsigned* p, unsigned v)
{
    asm volatile("st.release.gpu.global.u32 [%0], %1;" :: "l"(p), "r"(v) : "memory");
}

__device__ __forceinline__ void ffma2(unsigned long long& acc,
                                      unsigned long long a2,
                                      unsigned long long b2)
{
    asm("fma.rn.f32x2 %0, %1, %2, %0;" : "+l"(acc) : "l"(a2), "l"(b2));
}

__device__ __forceinline__ float rcpa(float x)
{
    float r; asm("rcp.approx.f32 %0, %1;" : "=f"(r) : "f"(x)); return r;
}
__device__ __forceinline__ float fsig(float x)  { return rcpa(1.0f + __expf(-x)); }
__device__ __forceinline__ float ftanh(float x) { return 2.0f * rcpa(1.0f + __expf(-2.0f * x)) - 1.0f; }

// 16 k-steps: lane tile 4m x 8n (16 packed f32x2 accumulators).
__device__ __forceinline__ void compute_chunk(const float* __restrict__ sa,
                                              const float* __restrict__ sw,
                                              unsigned long long acc[16])
{
#pragma unroll
    for (int r = 0; r < 16; ++r) {
        float2 a01 = *(const float2*)(sa + r * SA_STRIDE);
        float2 a23 = *(const float2*)(sa + r * SA_STRIDE + 2);
        const ulonglong2* bw = (const ulonglong2*)(sw + r * 32);
        ulonglong2 bv0 = bw[0];
        ulonglong2 bv1 = bw[1];
        unsigned long long a2_0, a2_1, a2_2, a2_3;
        asm("mov.b64 %0, {%1, %1};" : "=l"(a2_0) : "f"(a01.x));
        asm("mov.b64 %0, {%1, %1};" : "=l"(a2_1) : "f"(a01.y));
        asm("mov.b64 %0, {%1, %1};" : "=l"(a2_2) : "f"(a23.x));
        asm("mov.b64 %0, {%1, %1};" : "=l"(a2_3) : "f"(a23.y));
        ffma2(acc[0],  a2_0, bv0.x); ffma2(acc[1],  a2_0, bv0.y);
        ffma2(acc[2],  a2_0, bv1.x); ffma2(acc[3],  a2_0, bv1.y);
        ffma2(acc[4],  a2_1, bv0.x); ffma2(acc[5],  a2_1, bv0.y);
        ffma2(acc[6],  a2_1, bv1.x); ffma2(acc[7],  a2_1, bv1.y);
        ffma2(acc[8],  a2_2, bv0.x); ffma2(acc[9],  a2_2, bv0.y);
        ffma2(acc[10], a2_2, bv1.x); ffma2(acc[11], a2_2, bv1.y);
        ffma2(acc[12], a2_3, bv0.x); ffma2(acc[13], a2_3, bv0.y);
        ffma2(acc[14], a2_3, bv1.x); ffma2(acc[15], a2_3, bv1.y);
    }
}

// =====================================================================
// Persistent kernel: 512 x { GEMM -> e-exchange/pointwise -> barrier }.
// Gate block (stripe<64): z stays in smem; computes c,h for its
//   32 batches x 8 units with block-private mem shift register.
// ze block (stripe 64/65): publishes ze slice, does softmax, publishes e.
// =====================================================================
__global__ __launch_bounds__(256, 1) void xlstm_persistent(
    const float* __restrict__ x, float* __restrict__ out)
{
    extern __shared__ float smem[];
    float* s_W  = smem;
    float* s_aF = smem + SA_OFF;
    unsigned long long* s_p = (unsigned long long*)(smem + SA_OFF); // alias
    float* e_s  = smem + SA_OFF;                                    // alias (phase 2)
    float* s_z  = smem + SZ_OFF;
    float* s_mem = smem + SM_OFF;

    const int tid   = threadIdx.x;
    const int lane  = tid & 31;
    const int warp  = tid >> 5;           // k-group 0..7
    const int blk   = blockIdx.x;
    const int ST    = blk >> 1;           // stripe 0..65
    const int bh    = blk & 1;            // batch half
    const int n0    = ST * 32;
    const int m0    = bh * 32;
    const int si    = ST - 64;            // ze slice idx (valid if ST>=64)
    const int mq    = lane >> 2;          // 0..7
    const int nq    = lane & 3;           // 0..3
    const int qk    = nq * 4;
    const int kwarp = warp * 96;

    // ---- load W stripe into smem once
#pragma unroll 4
    for (int q = 0; q < 96; ++q) {
        int i = tid + q * 256;
        int k = i >> 5, n = i & 31;
        s_W[i] = g_W[k * NN + n0 + n];
    }
    // ---- zero block-private memory
    for (int i = tid; i < MM * 256; i += 256) s_mem[i] = 0.0f;

    // ---- hoist bias (packed cols n0+2np, n0+2np+1 ; np = tid&15 both halves)
    const float2 bias = *(const float2*)(g_b + n0 + 2 * (tid & 15));

    // ---- monotone flag bases (replay-safe) + epoch base
    const unsigned zbase = ld_acq(&g_zflag[0]);
    const unsigned ebase = ld_acq(&g_eflag[0]);
    unsigned my_epoch = ld_acq(&g_epoch);
    __syncthreads();

#define LOAD_CHUNK(cc)                                                        \
    {                                                                         \
        int kb = kwarp + (cc) * 16 + qk;                                      \
        if (kb < DD) {                                                        \
            const float* bp = x + (size_t)(m0 + mq) * (TT * DD)               \
                                + (size_t)t * DD + kb;                        \
            v0 = *(const float4*)(bp);                                        \
            v1 = *(const float4*)(bp + (size_t)8  * (TT * DD));               \
            v2 = *(const float4*)(bp + (size_t)16 * (TT * DD));               \
            v3 = *(const float4*)(bp + (size_t)24 * (TT * DD));               \
        } else {                                                              \
            const float* hp = g_h + (m0 + mq) * UU + (kb - DD);               \
            v0 = __ldcg((const float4*)(hp));                                 \
            v1 = __ldcg((const float4*)(hp + 8  * UU));                       \
            v2 = __ldcg((const float4*)(hp + 16 * UU));                       \
            v3 = __ldcg((const float4*)(hp + 24 * UU));                       \
        }                                                                     \
    }

#define STORE_CHUNK(bsel)                                                     \
    {                                                                         \
        float* d = s_aF + (bsel) * SA_BUF                                     \
                 + (warp * 16 + qk) * SA_STRIDE + mq;                         \
        d[0 * SA_STRIDE + 0]  = v0.x; d[1 * SA_STRIDE + 0]  = v0.y;           \
        d[2 * SA_STRIDE + 0]  = v0.z; d[3 * SA_STRIDE + 0]  = v0.w;           \
        d[0 * SA_STRIDE + 8]  = v1.x; d[1 * SA_STRIDE + 8]  = v1.y;           \
        d[2 * SA_STRIDE + 8]  = v1.z; d[3 * SA_STRIDE + 8]  = v1.w;           \
        d[0 * SA_STRIDE + 16] = v2.x; d[1 * SA_STRIDE + 16] = v2.y;           \
        d[2 * SA_STRIDE + 16] = v2.z; d[3 * SA_STRIDE + 16] = v2.w;           \
        d[0 * SA_STRIDE + 24] = v3.x; d[1 * SA_STRIDE + 24] = v3.y;           \
        d[2 * SA_STRIDE + 24] = v3.z; d[3 * SA_STRIDE + 24] = v3.w;           \
    }

    for (int t = 0; t < TT; ++t) {
        const unsigned ztarget = zbase + (unsigned)t + 1u;
        const unsigned etarget = ebase + (unsigned)t + 1u;

        // ============================ GEMM ============================
        unsigned long long acc[16];
#pragma unroll
        for (int q = 0; q < 16; ++q) acc[q] = 0ull;

        float4 v0, v1, v2, v3;
        LOAD_CHUNK(0)

#pragma unroll 1
        for (int c = 0; c < 6; ++c) {
            STORE_CHUNK(c & 1)
            __syncthreads();
            if (c < 5) LOAD_CHUNK(c + 1)
            compute_chunk(s_aF + (c & 1) * SA_BUF + (warp * 16) * SA_STRIDE + 4 * mq,
                          s_W + (kwarp + c * 16) * 32 + 8 * nq, acc);
        }

        // ---- cross-kg reduction
        __syncthreads();
        {
            unsigned long long* pp = s_p + (size_t)tid * 17;
#pragma unroll
            for (int q = 0; q < 16; ++q) pp[q] = acc[q];
        }
        __syncthreads();
#pragma unroll
        for (int q2 = 0; q2 < 2; ++q2) {
            int o   = tid + q2 * 256;
            int m   = o >> 4;
            int np  = o & 15;
            int src = (4 * (m >> 2) + (np >> 2)) * 17 + (m & 3) * 4 + (np & 3);
            float sx0 = 0.f, sy0 = 0.f, sx1 = 0.f, sy1 = 0.f;
#pragma unroll
            for (int kg = 0; kg < 8; kg += 2) {
                unsigned long long u0 = s_p[(size_t)(kg * 32) * 17 + src];
                unsigned long long u1 = s_p[(size_t)((kg + 1) * 32) * 17 + src];
                float l0, h0, l1, h1;
                asm("mov.b64 {%0, %1}, %2;" : "=f"(l0), "=f"(h0) : "l"(u0));
                asm("mov.b64 {%0, %1}, %2;" : "=f"(l1), "=f"(h1) : "l"(u1));
                sx0 += l0; sy0 += h0;
                sx1 += l1; sy1 += h1;
            }
            float2 r;
            r.x = (sx0 + sx1) + bias.x;
            r.y = (sy0 + sy1) + bias.y;
            if (ST < 64) {
                *(float2*)(s_z + m * 34 + 2 * np) = r;          // z stays local
            } else {
                *(float2*)(g_zes + (size_t)(((bh * 2 + si) * 32 + m) * 32 + 2 * np)) = r;
            }
        }
        __syncthreads();   // z tile complete; s_p reads done (e_s may overwrite)

        if (ST >= 64) {
            // =================== ze block: softmax producer ===========
            if (tid == 0) st_rel(&g_zflag[(bh * 2 + si) * 8], ztarget);
            if (tid == 0) {
                while ((int)(ld_acq(&g_zflag[(bh * 2 + 0) * 8]) - ztarget) < 0) { }
                while ((int)(ld_acq(&g_zflag[(bh * 2 + 1) * 8]) - ztarget) < 0) { }
            }
            __syncthreads();
            // 8 warps x 2 batches each = 16 batches for this producer
#pragma unroll
            for (int rr = 0; rr < 2; ++rr) {
                int rloc = si * 16 + warp * 2 + rr;       // 0..31 within half
                float z0 = __ldcg(&g_zes[((bh * 2 + 0) * 32 + rloc) * 32 + lane]);
                float z1 = __ldcg(&g_zes[((bh * 2 + 1) * 32 + rloc) * 32 + lane]);
                float mx = fmaxf(z0, z1);
#pragma unroll
                for (int o = 16; o > 0; o >>= 1)
                    mx = fmaxf(mx, __shfl_xor_sync(0xffffffffu, mx, o));
                float e0 = __expf(z0 - mx);
                float e1 = __expf(z1 - mx);
                float sm2 = e0 + e1;
#pragma unroll
                for (int o = 16; o > 0; o >>= 1)
                    sm2 += __shfl_xor_sync(0xffffffffu, sm2, o);
                float inv = rcpa(sm2);
                g_e[(bh * 32 + rloc) * 64 + lane]      = e0 * inv;
                g_e[(bh * 32 + rloc) * 64 + 32 + lane] = e1 * inv;
            }
            __syncthreads();
            if (tid == 0) st_rel(&g_eflag[(bh * 2 + si) * 8], etarget);
        } else {
            // =================== gate block: pointwise ================
            const int pm = tid >> 3;      // 0..31 batch row (local)
            const int pu = tid & 7;       // 0..7 unit offset
            float gi = fsig (s_z[pm * 34 +      pu]);
            float gf = fsig (s_z[pm * 34 +  8 + pu]);
            float go = fsig (s_z[pm * 34 + 16 + pu]);
            float ct = ftanh(s_z[pm * 34 + 24 + pu]);

            if (tid == 0) {
                while ((int)(ld_acq(&g_eflag[(bh * 2 + 0) * 8]) - etarget) < 0) { }
                while ((int)(ld_acq(&g_eflag[(bh * 2 + 1) * 8]) - etarget) < 0) { }
            }
            __syncthreads();
            // stage e[32][64] -> e_s padded [32][66]
#pragma unroll
            for (int q = 0; q < 8; ++q) {
                int idx = tid + q * 256;          // 0..2047
                int em = idx >> 6, es = idx & 63;
                e_s[em * 66 + es] = __ldcg(&g_e[(bh * 32 + em) * 64 + es]);
            }
            __syncthreads();

            const float* ew = e_s + pm * 66;
            float c0 = 0.f, c1 = 0.f, c2 = 0.f, c3 = 0.f;
#pragma unroll
            for (int a = 0; a < MM; a += 4) {
                c0 += ew[a + 0] * s_mem[(((t - 1 - a - 0) & 63) * 256) + tid];
                c1 += ew[a + 1] * s_mem[(((t - 1 - a - 1) & 63) * 256) + tid];
                c2 += ew[a + 2] * s_mem[(((t - 1 - a - 2) & 63) * 256) + tid];
                c3 += ew[a + 3] * s_mem[(((t - 1 - a - 3) & 63) * 256) + tid];
            }
            float contrib = (c0 + c1) + (c2 + c3);

            float cc = gf * contrib + gi * ct;
            float hh = go * ftanh(cc);

            s_mem[(t & 63) * 256 + tid] = cc;     // overwrite oldest slot
            int ug = ST * 8 + pu;
            g_h[(bh * 32 + pm) * UU + ug] = hh;
            out[(size_t)(bh * 32 + pm) * (TT * UU) + (size_t)t * UU + ug] = hh;
        }

        grid_barrier(&my_epoch);      // single barrier per step (h visibility)
    }
#undef LOAD_CHUNK
#undef STORE_CHUNK
}

// =====================================================================
// Launch: 2 graph nodes. No allocations, graph-capturable.
// =====================================================================
extern "C" void kernel_launch(void* const* d_in, const int* in_sizes, int n_in,
                              void* d_out, int out_size)
{
    (void)in_sizes; (void)n_in; (void)out_size;
    const float* x  = (const float*)d_in[0];
    const float* Wi = (const float*)d_in[1];
    const float* Ui = (const float*)d_in[2];
    const float* bi = (const float*)d_in[3];
    const float* Wf = (const float*)d_in[4];
    const float* Uf = (const float*)d_in[5];
    const float* bf = (const float*)d_in[6];
    const float* Wo = (const float*)d_in[7];
    const float* Uo = (const float*)d_in[8];
    const float* bo = (const float*)d_in[9];
    const float* Wc = (const float*)d_in[10];
    const float* Uc = (const float*)d_in[11];
    const float* bc = (const float*)d_in[12];
    const float* We = (const float*)d_in[13];
    const float* Ue = (const float*)d_in[14];
    const float* be = (const float*)d_in[15];
    float* out = (float*)d_out;

    cudaFuncSetAttribute(xlstm_persistent,
                         cudaFuncAttributeMaxDynamicSharedMemorySize, SMEM_BYTES);

    init_kernel<<<1024, 256>>>(Wi, Ui, bi, Wf, Uf, bf, Wo, Uo, bo,
                               Wc, Uc, bc, We, Ue, be);
    xlstm_persistent<<<NBLK, 256, SMEM_BYTES>>>(x, out);
}

// round 13
// speedup vs baseline: 1.5153x; 1.2292x over previous
#include <cuda_runtime.h>
#include <cstdint>

// Problem constants
#define BB 64      // batch
#define TT 512     // seq len
#define DD 256     // input dim
#define UU 512     // units
#define MM 64      // memory slots
#define NN 2112    // 4*U + M
#define KK 768     // D + U

#define NBLK 132   // 66 n-stripes x 2 batch-halves

// dynamic smem layout (float offsets)
//  s_W   : [768][32]              24576 f  (persistent weight stripe)
//  s_a   : 2 x [128][34]           8704 f  (A double buffer; aliased by s_p: 256x17 u64)
//  s_mem : [64][256]              16384 f  (block-private shift-register memory)
#define SA_STRIDE 34
#define SA_BUF 4352
#define SA_OFF 24576
#define SM_OFF 33280
#define SMEM_FLOATS 49664
#define SMEM_BYTES (SMEM_FLOATS * 4)   // 198656 B

// -------- device scratch (no allocations allowed) --------
__device__ float g_W[KK * NN];
__device__ float g_b[NN];
__device__ float g_h[BB * UU];
__device__ float g_z[BB * NN];
__device__ unsigned g_count = 0;
__device__ unsigned g_epoch = 0;

// =====================================================================
// Init: pack W/U/b into [768 x 2112], zero h.
// =====================================================================
__global__ void init_kernel(
    const float* __restrict__ Wi, const float* __restrict__ Ui, const float* __restrict__ bi,
    const float* __restrict__ Wf, const float* __restrict__ Uf, const float* __restrict__ bf,
    const float* __restrict__ Wo, const float* __restrict__ Uo, const float* __restrict__ bo,
    const float* __restrict__ Wc, const float* __restrict__ Uc, const float* __restrict__ bc,
    const float* __restrict__ We, const float* __restrict__ Ue, const float* __restrict__ be)
{
    int stride = gridDim.x * blockDim.x;
    int t0 = blockIdx.x * blockDim.x + threadIdx.x;

    for (int i = t0; i < KK * NN; i += stride) {
        int k = i / NN;
        int n = i - k * NN;
        float v;
        if (n < 4 * UU) {
            int g = n >> 9;
            int col = n & (UU - 1);
            const float* s;
            if (k < DD) {
                s = (g == 0) ? Wi : (g == 1) ? Wf : (g == 2) ? Wo : Wc;
                v = s[k * UU + col];
            } else {
                s = (g == 0) ? Ui : (g == 1) ? Uf : (g == 2) ? Uo : Uc;
                v = s[(k - DD) * UU + col];
            }
        } else {
            int col = n - 4 * UU;
            v = (k < DD) ? We[k * MM + col] : Ue[(k - DD) * MM + col];
        }
        g_W[i] = v;
    }
    for (int i = t0; i < NN; i += stride) {
        float v;
        if (i < 4 * UU) {
            int g = i >> 9;
            int col = i & (UU - 1);
            v = (g == 0) ? bi[col] : (g == 1) ? bf[col] : (g == 2) ? bo[col] : bc[col];
        } else {
            v = be[i - 4 * UU];
        }
        g_b[i] = v;
    }
    for (int i = t0; i < BB * UU; i += stride) g_h[i] = 0.0f;
}

// =====================================================================
// Grid-wide barrier: acq_rel arrival, release epoch, acquire spin.
// (Best-measured version from R8.)
// =====================================================================
__device__ __forceinline__ void grid_barrier(unsigned* my_epoch)
{
    __syncthreads();
    if (threadIdx.x == 0) {
        unsigned target = *my_epoch + 1u;
        unsigned v;
        asm volatile("atom.acq_rel.gpu.global.add.u32 %0, [%1], 1;"
                     : "=r"(v) : "l"(&g_count) : "memory");
        if (v == NBLK - 1) {
            unsigned zero = 0;
            asm volatile("st.relaxed.gpu.global.u32 [%0], %1;"
                         :: "l"(&g_count), "r"(zero) : "memory");
            asm volatile("st.release.gpu.global.u32 [%0], %1;"
                         :: "l"(&g_epoch), "r"(target) : "memory");
        } else {
            unsigned e;
            do {
                asm volatile("ld.acquire.gpu.global.u32 %0, [%1];"
                             : "=r"(e) : "l"(&g_epoch) : "memory");
            } while ((int)(e - target) < 0);
        }
        *my_epoch = target;
    }
    __syncthreads();
}

__device__ __forceinline__ void ffma2(unsigned long long& acc,
                                      unsigned long long a2,
                                      unsigned long long b2)
{
    asm("fma.rn.f32x2 %0, %1, %2, %0;" : "+l"(acc) : "l"(a2), "l"(b2));
}

__device__ __forceinline__ float rcpa(float x)
{
    float r; asm("rcp.approx.f32 %0, %1;" : "=f"(r) : "f"(x)); return r;
}
__device__ __forceinline__ float fsig(float x)  { return rcpa(1.0f + __expf(-x)); }
__device__ __forceinline__ float ftanh(float x) { return 2.0f * rcpa(1.0f + __expf(-2.0f * x)) - 1.0f; }

// 16 k-steps: lane tile 4m x 8n (16 packed f32x2 accumulators).
// acc[mi*4+p] = m row (4*mq+mi), packed n cols (8*nq+2p, 8*nq+2p+1).
__device__ __forceinline__ void compute_chunk(const float* __restrict__ sa,
                                              const float* __restrict__ sw,
                                              unsigned long long acc[16])
{
#pragma unroll
    for (int r = 0; r < 16; ++r) {
        float2 a01 = *(const float2*)(sa + r * SA_STRIDE);
        float2 a23 = *(const float2*)(sa + r * SA_STRIDE + 2);
        const ulonglong2* bw = (const ulonglong2*)(sw + r * 32);
        ulonglong2 bv0 = bw[0];
        ulonglong2 bv1 = bw[1];
        unsigned long long a2_0, a2_1, a2_2, a2_3;
        asm("mov.b64 %0, {%1, %1};" : "=l"(a2_0) : "f"(a01.x));
        asm("mov.b64 %0, {%1, %1};" : "=l"(a2_1) : "f"(a01.y));
        asm("mov.b64 %0, {%1, %1};" : "=l"(a2_2) : "f"(a23.x));
        asm("mov.b64 %0, {%1, %1};" : "=l"(a2_3) : "f"(a23.y));
        ffma2(acc[0],  a2_0, bv0.x); ffma2(acc[1],  a2_0, bv0.y);
        ffma2(acc[2],  a2_0, bv1.x); ffma2(acc[3],  a2_0, bv1.y);
        ffma2(acc[4],  a2_1, bv0.x); ffma2(acc[5],  a2_1, bv0.y);
        ffma2(acc[6],  a2_1, bv1.x); ffma2(acc[7],  a2_1, bv1.y);
        ffma2(acc[8],  a2_2, bv0.x); ffma2(acc[9],  a2_2, bv0.y);
        ffma2(acc[10], a2_2, bv1.x); ffma2(acc[11], a2_2, bv1.y);
        ffma2(acc[12], a2_3, bv0.x); ffma2(acc[13], a2_3, bv0.y);
        ffma2(acc[14], a2_3, bv1.x); ffma2(acc[15], a2_3, bv1.y);
    }
}

// =====================================================================
// Persistent kernel. Chunk c covers global k in [c*128, c*128+128);
// within a chunk, warp w owns k-local [16w, 16w+16).
// Chunks 0-1 are pure-x (k<256, h-INDEPENDENT); chunks 2-5 pure-h.
// Step pipeline:  [accs hold x(t)] -> h-chunks(t) -> epilogue -> z(t)
//   -> barrier -> prefetch-x-LDG(t+1) -> pointwise(t) -> x-chunks(t+1)
//   -> barrier.  x-work rides in the pointwise/skew window; its
//   partials stay in the accumulators across the barriers.
// =====================================================================
__global__ __launch_bounds__(256, 1) void xlstm_persistent(
    const float* __restrict__ x, float* __restrict__ out)
{
    extern __shared__ float smem[];
    float* s_W  = smem;
    float* s_aF = smem + SA_OFF;
    unsigned long long* s_p  = (unsigned long long*)(smem + SA_OFF); // alias
    float* s_mem = smem + SM_OFF;
    __shared__ float s_e[MM];
    __shared__ float s_ew[MM];

    const int tid   = threadIdx.x;
    const int lane  = tid & 31;
    const int warp  = tid >> 5;
    const int blk   = blockIdx.x;
    const int n0    = (blk >> 1) * 32;
    const int m0    = (blk & 1) * 32;
    const int mq    = lane >> 2;          // 0..7
    const int nq    = lane & 3;           // 0..3
    const int qk    = nq * 4;             // k offset of this lane's float4

    // ---- load W stripe into smem once (persistent across all 512 steps)
#pragma unroll 4
    for (int q = 0; q < 96; ++q) {
        int i = tid + q * 256;            // 0..24575
        int k = i >> 5, n = i & 31;
        s_W[i] = g_W[k * NN + n0 + n];
    }
    // ---- zero block-private memory
    for (int i = tid; i < MM * 256; i += 256) s_mem[i] = 0.0f;

    // ---- hoist bias for this thread's two epilogue outputs
    float2 bias0 = *(const float2*)(g_b + n0 + 2 * (tid & 15));

    unsigned my_epoch;
    {
        unsigned e0;
        asm volatile("ld.acquire.gpu.global.u32 %0, [%1];"
                     : "=r"(e0) : "l"(&g_epoch) : "memory");
        my_epoch = e0;
    }
    __syncthreads();

// x chunk (cc in {0,1}): global k = cc*128 + warp*16 + qk  (< 256)
#define LOAD_X(cc, ts)                                                        \
    {                                                                         \
        int kb = (cc) * 128 + warp * 16 + qk;                                 \
        const float* bp = x + (size_t)(m0 + mq) * (TT * DD)                   \
                            + (size_t)(ts) * DD + kb;                         \
        v0 = *(const float4*)(bp);                                            \
        v1 = *(const float4*)(bp + (size_t)8  * (TT * DD));                   \
        v2 = *(const float4*)(bp + (size_t)16 * (TT * DD));                   \
        v3 = *(const float4*)(bp + (size_t)24 * (TT * DD));                   \
    }

// h chunk (cc in {2..5}): global k = cc*128 + warp*16 + qk, h idx = k-256
#define LOAD_H(cc)                                                            \
    {                                                                         \
        int kh = (cc) * 128 + warp * 16 + qk - DD;                            \
        const float* hp = g_h + (m0 + mq) * UU + kh;                          \
        v0 = __ldcg((const float4*)(hp));                                     \
        v1 = __ldcg((const float4*)(hp + 8  * UU));                          \
        v2 = __ldcg((const float4*)(hp + 16 * UU));                          \
        v3 = __ldcg((const float4*)(hp + 24 * UU));                          \
    }

#define STORE_CHUNK(bsel)                                                     \
    {                                                                         \
        float* d = s_aF + (bsel) * SA_BUF                                     \
                 + (warp * 16 + qk) * SA_STRIDE + mq;                         \
        d[0 * SA_STRIDE + 0]  = v0.x; d[1 * SA_STRIDE + 0]  = v0.y;           \
        d[2 * SA_STRIDE + 0]  = v0.z; d[3 * SA_STRIDE + 0]  = v0.w;           \
        d[0 * SA_STRIDE + 8]  = v1.x; d[1 * SA_STRIDE + 8]  = v1.y;           \
        d[2 * SA_STRIDE + 8]  = v1.z; d[3 * SA_STRIDE + 8]  = v1.w;           \
        d[0 * SA_STRIDE + 16] = v2.x; d[1 * SA_STRIDE + 16] = v2.y;           \
        d[2 * SA_STRIDE + 16] = v2.z; d[3 * SA_STRIDE + 16] = v2.w;           \
        d[0 * SA_STRIDE + 24] = v3.x; d[1 * SA_STRIDE + 24] = v3.y;           \
        d[2 * SA_STRIDE + 24] = v3.z; d[3 * SA_STRIDE + 24] = v3.w;           \
    }

#define COMPUTE(cc, bsel)                                                     \
    compute_chunk(s_aF + (bsel) * SA_BUF + (warp * 16) * SA_STRIDE + 4 * mq,  \
                  s_W + ((cc) * 128 + warp * 16) * 32 + 8 * nq, acc);

    unsigned long long acc[16];
#pragma unroll
    for (int q = 0; q < 16; ++q) acc[q] = 0ull;

    float4 v0, v1, v2, v3;

    // ---- prologue: x-part of step 0 into accs
    LOAD_X(0, 0)
    STORE_CHUNK(0)
    __syncthreads();
    LOAD_X(1, 0)
    COMPUTE(0, 0)
    STORE_CHUNK(1)
    __syncthreads();
    COMPUTE(1, 1)

    for (int t = 0; t < TT; ++t) {
        // ================= h-part GEMM (chunks 2..5) ==================
        LOAD_H(2)
        STORE_CHUNK(0)
        __syncthreads();
        LOAD_H(3)
        COMPUTE(2, 0)
        STORE_CHUNK(1)
        __syncthreads();
        LOAD_H(4)
        COMPUTE(3, 1)
        STORE_CHUNK(0)
        __syncthreads();
        LOAD_H(5)
        COMPUTE(4, 0)
        STORE_CHUNK(1)
        __syncthreads();
        COMPUTE(5, 1)

        // ---- cross-warp reduction (x+h partials together)
        __syncthreads();
        {
            unsigned long long* pp = s_p + (size_t)tid * 17;
#pragma unroll
            for (int q = 0; q < 16; ++q) pp[q] = acc[q];
        }
        __syncthreads();
#pragma unroll
        for (int q2 = 0; q2 < 2; ++q2) {
            int o   = tid + q2 * 256;     // 0..511
            int m   = o >> 4;             // 0..31
            int np  = o & 15;             // u64 col pair
            int src = (4 * (m >> 2) + (np >> 2)) * 17 + (m & 3) * 4 + (np & 3);
            float sx0 = 0.f, sy0 = 0.f, sx1 = 0.f, sy1 = 0.f;
#pragma unroll
            for (int kg = 0; kg < 8; kg += 2) {
                unsigned long long u0 = s_p[(size_t)(kg * 32) * 17 + src];
                unsigned long long u1 = s_p[(size_t)((kg + 1) * 32) * 17 + src];
                float l0, h0, l1, h1;
                asm("mov.b64 {%0, %1}, %2;" : "=f"(l0), "=f"(h0) : "l"(u0));
                asm("mov.b64 {%0, %1}, %2;" : "=f"(l1), "=f"(h1) : "l"(u1));
                sx0 += l0; sy0 += h0;
                sx1 += l1; sy1 += h1;
            }
            float2 r;
            r.x = (sx0 + sx1) + bias0.x;
            r.y = (sy0 + sy1) + bias0.y;
            *(float2*)(g_z + (size_t)(m0 + m) * NN + n0 + 2 * np) = r;
        }

        grid_barrier(&my_epoch);

        // ---- prefetch next step's first x chunk (flies under pointwise)
        const int tn = (t + 1) & (TT - 1);    // t=511 wraps to 0 (safe, unused)
        LOAD_X(0, tn)

        // ========================== pointwise =========================
        if (blk < 2 * BB) {
            const int b    = blk >> 1;
            const int half = blk & 1;

            if (tid < 32) {
                float z0 = __ldcg(&g_z[b * NN + 4 * UU + tid]);
                float z1 = __ldcg(&g_z[b * NN + 4 * UU + 32 + tid]);
                float mx = fmaxf(z0, z1);
#pragma unroll
                for (int o = 16; o > 0; o >>= 1)
                    mx = fmaxf(mx, __shfl_xor_sync(0xffffffffu, mx, o));
                float e0 = __expf(z0 - mx);
                float e1 = __expf(z1 - mx);
                float sm2 = e0 + e1;
#pragma unroll
                for (int o = 16; o > 0; o >>= 1)
                    sm2 += __shfl_xor_sync(0xffffffffu, sm2, o);
                float inv = rcpa(sm2);
                s_e[tid]      = e0 * inv;
                s_e[tid + 32] = e1 * inv;
            }
            __syncthreads();
            if (tid < MM) s_ew[tid] = s_e[(t - 1 - tid) & (MM - 1)];
            __syncthreads();

            const int u  = half * 256 + tid;
            const int zb = b * NN;
            float zi = __ldcg(&g_z[zb + u]);
            float zf = __ldcg(&g_z[zb + UU + u]);
            float zo = __ldcg(&g_z[zb + 2 * UU + u]);
            float zc = __ldcg(&g_z[zb + 3 * UU + u]);

            float gi = fsig(zi);
            float gf = fsig(zf);
            float go = fsig(zo);
            float ct = ftanh(zc);

            const float* mb = s_mem + tid;
            float c0 = 0.f, c1 = 0.f, c2 = 0.f, c3 = 0.f;
#pragma unroll
            for (int s = 0; s < MM; s += 4) {
                c0 += s_ew[s + 0] * mb[(s + 0) * 256];
                c1 += s_ew[s + 1] * mb[(s + 1) * 256];
                c2 += s_ew[s + 2] * mb[(s + 2) * 256];
                c3 += s_ew[s + 3] * mb[(s + 3) * 256];
            }
            float contrib = (c0 + c1) + (c2 + c3);

            float cc = gf * contrib + gi * ct;
            float hh = go * ftanh(cc);

            s_mem[(t & (MM - 1)) * 256 + tid] = cc;   // overwrite oldest slot
            g_h[b * UU + u] = hh;
            out[(size_t)b * (TT * UU) + (size_t)t * UU + u] = hh;
        }

        // ============== x-part GEMM for step t+1 (off critical path) ==
#pragma unroll
        for (int q = 0; q < 16; ++q) acc[q] = 0ull;
        STORE_CHUNK(0)
        __syncthreads();
        LOAD_X(1, tn)
        COMPUTE(0, 0)
        STORE_CHUNK(1)
        __syncthreads();
        COMPUTE(1, 1)

        grid_barrier(&my_epoch);
    }
#undef LOAD_X
#undef LOAD_H
#undef STORE_CHUNK
#undef COMPUTE
}

// =====================================================================
// Launch: 2 graph nodes. No allocations, graph-capturable.
// =====================================================================
extern "C" void kernel_launch(void* const* d_in, const int* in_sizes, int n_in,
                              void* d_out, int out_size)
{
    (void)in_sizes; (void)n_in; (void)out_size;
    const float* x  = (const float*)d_in[0];
    const float* Wi = (const float*)d_in[1];
    const float* Ui = (const float*)d_in[2];
    const float* bi = (const float*)d_in[3];
    const float* Wf = (const float*)d_in[4];
    const float* Uf = (const float*)d_in[5];
    const float* bf = (const float*)d_in[6];
    const float* Wo = (const float*)d_in[7];
    const float* Uo = (const float*)d_in[8];
    const float* bo = (const float*)d_in[9];
    const float* Wc = (const float*)d_in[10];
    const float* Uc = (const float*)d_in[11];
    const float* bc = (const float*)d_in[12];
    const float* We = (const float*)d_in[13];
    const float* Ue = (const float*)d_in[14];
    const float* be = (const float*)d_in[15];
    float* out = (float*)d_out;

    cudaFuncSetAttribute(xlstm_persistent,
                         cudaFuncAttributeMaxDynamicSharedMemorySize, SMEM_BYTES);

    init_kernel<<<1024, 256>>>(Wi, Ui, bi, Wf, Uf, bf, Wo, Uo, bo,
                               Wc, Uc, bc, We, Ue, be);
    xlstm_persistent<<<NBLK, 256, SMEM_BYTES>>>(x, out);
}